// round 14
// baseline (speedup 1.0000x reference)
#include <cuda_runtime.h>
#include <cuda_bf16.h>

// MultiHeadSpMM: out[r, h*D+d] = sum_{e: row[e]==r} attention[e,h] * h[col[e],h,d]
// N=100000, E=1600000, H=4, D=8 (H*D == 32). row[] is sorted.
//
// R14: wavefront-optimal layout. One warp per row; group g = lane>>3 works on
//   edge e+g (CONSECUTIVE edges of the same row), lane q = lane&7 holds
//   features [4q,4q+4) as float4 (head hd=q>>1).
//   L1 wavefronts per 8 edges: col 1 (32B), att 2 (64B each), hfeat 8
//   (irreducible) = 1.4 wf/edge, vs 2.25 in the R10 multi-row layout.
//   Main loop unpredicated over 8-aligned edge count; one predicated tail
//   batch. __launch_bounds__(256,6) -> 42-reg budget for true 8-line MLP
//   without the occupancy collapse of (256,5).
//   Epilogue: 2 shfl-xor float4 reductions; lanes 0-7 store the row (1 wf).

#define MAX_NODES (1 << 21)

__device__ int g_row_ptr[MAX_NODES + 1];

__global__ void build_row_ptr_kernel(const int* __restrict__ row, int E, int N) {
    int e = blockIdx.x * blockDim.x + threadIdx.x;
    if (e >= E) return;
    int r = row[e];
    if (r < 0) r = 0;
    if (r >= N) r = N - 1;
    int prev;
    if (e == 0) {
        prev = -1;
    } else {
        prev = row[e - 1];
        if (prev < 0) prev = 0;
        if (prev >= N) prev = N - 1;
    }
    for (int i = prev + 1; i <= r; ++i) g_row_ptr[i] = e;
    if (e == E - 1) {
        for (int i = r + 1; i <= N; ++i) g_row_ptr[i] = E;
    }
}

__global__ __launch_bounds__(256, 6) void spmm_rowwarp_kernel(
    const int* __restrict__ col,
    const float* __restrict__ att,   // (E, 4)
    const float* __restrict__ hfeat, // (N, 32)
    float* __restrict__ out,         // (N, 32)
    int N)
{
    int warp = (blockIdx.x * blockDim.x + threadIdx.x) >> 5;
    int lane = threadIdx.x & 31;
    if (warp >= N) return;          // warp-uniform; safe before shfls

    const int beg = g_row_ptr[warp];
    const int end = g_row_ptr[warp + 1];
    const int deg = end - beg;

    const int g  = lane >> 3;       // edge slot 0..3 within batch of 4
    const int q  = lane & 7;        // feature quarter
    const int hd = q >> 1;          // head for this quarter
    const int nmax = N - 1;

    float4 acc = make_float4(0.f, 0.f, 0.f, 0.f);

    // ---- Unpredicated main loop: 8 consecutive edges per iteration ----
    const int full = beg + (deg & ~7);
    for (int e = beg; e < full; e += 8) {
        int e0 = e + g;
        int e1 = e + 4 + g;

        int c0 = __ldg(&col[e0]);
        int c1 = __ldg(&col[e1]);
        c0 = min(max(c0, 0), nmax);
        c1 = min(max(c1, 0), nmax);

        float a0 = __ldg(&att[e0 * 4 + hd]);
        float a1 = __ldg(&att[e1 * 4 + hd]);

        float4 h0 = __ldg((const float4*)(hfeat + c0 * 32 + q * 4));
        float4 h1 = __ldg((const float4*)(hfeat + c1 * 32 + q * 4));

        acc.x = fmaf(a0, h0.x, acc.x);
        acc.y = fmaf(a0, h0.y, acc.y);
        acc.z = fmaf(a0, h0.z, acc.z);
        acc.w = fmaf(a0, h0.w, acc.w);
        acc.x = fmaf(a1, h1.x, acc.x);
        acc.y = fmaf(a1, h1.y, acc.y);
        acc.z = fmaf(a1, h1.z, acc.z);
        acc.w = fmaf(a1, h1.w, acc.w);
    }

    // ---- Predicated tail: up to 7 edges ----
    if (full < end) {
        int e0 = full + g;
        int e1 = full + 4 + g;
        bool v0 = (e0 < end);
        bool v1 = (e1 < end);
        int s0 = v0 ? e0 : beg;     // beg valid whenever deg > 0
        int s1 = v1 ? e1 : beg;

        int c0 = __ldg(&col[s0]);
        int c1 = __ldg(&col[s1]);
        c0 = min(max(c0, 0), nmax);
        c1 = min(max(c1, 0), nmax);

        float a0 = v0 ? __ldg(&att[s0 * 4 + hd]) : 0.f;
        float a1 = v1 ? __ldg(&att[s1 * 4 + hd]) : 0.f;

        float4 h0 = __ldg((const float4*)(hfeat + c0 * 32 + q * 4));
        float4 h1 = __ldg((const float4*)(hfeat + c1 * 32 + q * 4));

        acc.x = fmaf(a0, h0.x, acc.x);
        acc.y = fmaf(a0, h0.y, acc.y);
        acc.z = fmaf(a0, h0.z, acc.z);
        acc.w = fmaf(a0, h0.w, acc.w);
        acc.x = fmaf(a1, h1.x, acc.x);
        acc.y = fmaf(a1, h1.y, acc.y);
        acc.z = fmaf(a1, h1.z, acc.z);
        acc.w = fmaf(a1, h1.w, acc.w);
    }

    // ---- Reduce the 4 edge-group partials (lanes q, q+8, q+16, q+24) ----
    const unsigned FULL_MASK = 0xffffffffu;
    #pragma unroll
    for (int m = 8; m <= 16; m <<= 1) {
        acc.x += __shfl_xor_sync(FULL_MASK, acc.x, m);
        acc.y += __shfl_xor_sync(FULL_MASK, acc.y, m);
        acc.z += __shfl_xor_sync(FULL_MASK, acc.z, m);
        acc.w += __shfl_xor_sync(FULL_MASK, acc.w, m);
    }

    if (lane < 8) {
        ((float4*)out)[warp * 8 + lane] = acc;  // one 128B line per row
    }
}

extern "C" void kernel_launch(void* const* d_in, const int* in_sizes, int n_in,
                              void* d_out, int out_size) {
    const int*   row  = (const int*)  d_in[0];
    const int*   col  = (const int*)  d_in[1];
    const float* att  = (const float*)d_in[2];
    const float* hft  = (const float*)d_in[3];
    float*       out  = (float*)      d_out;

    int E = in_sizes[0];
    int N = in_sizes[3] / 32;  // h is (N, 4, 8)

    {
        int threads = 256;
        int blocks = (E + threads - 1) / threads;
        build_row_ptr_kernel<<<blocks, threads>>>(row, E, N);
    }
    {
        int threads = 256;  // 8 warps per block, one warp per row
        int blocks = (N * 32 + threads - 1) / threads;
        spmm_rowwarp_kernel<<<blocks, threads>>>(col, att, hft, out, N);
    }
}

// round 15
// speedup vs baseline: 1.2797x; 1.2797x over previous
#include <cuda_runtime.h>
#include <cuda_bf16.h>

// MultiHeadSpMM: out[r, h*D+d] = sum_{e: row[e]==r} attention[e,h] * h[col[e],h,d]
// N=100000, E=1600000, H=4, D=8 (H*D == 32). row[] is sorted.
//
// R15: R10 (measured best skeleton, 27.5us kernel) with two occupancy-neutral
//   tweaks:
//   (1) 64-thread blocks: same 2048-thr/SM cap (32 CTAs), but 4x lower
//       per-block duration variance -> less wave-tail idle (R10 occ was 79%).
//   (2) att LDGs hoisted before the clamp+hfeat sequence: att/col stream from
//       DRAM (~577cyc) while hfeat hits L2 (~240cyc); issue the long-pole
//       loads first so they overlap the gathers.
//   Hot loop otherwise byte-identical to R10; regs must stay 32.

#define MAX_NODES (1 << 21)

__device__ int g_row_ptr[MAX_NODES + 1];

__global__ void build_row_ptr_kernel(const int* __restrict__ row, int E, int N) {
    int e = blockIdx.x * blockDim.x + threadIdx.x;
    if (e >= E) return;
    int r = row[e];
    if (r < 0) r = 0;
    if (r >= N) r = N - 1;
    int prev;
    if (e == 0) {
        prev = -1;
    } else {
        prev = row[e - 1];
        if (prev < 0) prev = 0;
        if (prev >= N) prev = N - 1;
    }
    for (int i = prev + 1; i <= r; ++i) g_row_ptr[i] = e;
    if (e == E - 1) {
        for (int i = r + 1; i <= N; ++i) g_row_ptr[i] = E;
    }
}

__global__ __launch_bounds__(64) void spmm_group_div_kernel(
    const int* __restrict__ col,
    const float* __restrict__ att,   // (E, 4)
    const float* __restrict__ hfeat, // (N, 32)
    float* __restrict__ out,         // (N, 32)
    int N)
{
    int warp = (blockIdx.x * blockDim.x + threadIdx.x) >> 5;
    int lane = threadIdx.x & 31;

    const int g  = lane >> 3;       // group 0..3 -> row
    const int q  = lane & 7;        // feature quarter
    const int hd = q >> 1;          // head for this quarter
    const int r  = warp * 4 + g;
    if (r >= N) return;             // no sync/shfl below: early exit is safe

    const int beg = g_row_ptr[r];
    const int end = g_row_ptr[r + 1];
    const int nmax = N - 1;

    float4 acc = make_float4(0.f, 0.f, 0.f, 0.f);

    int e = beg;
    // Unpredicated 4-edge unroll; groups diverge naturally.
    for (; e + 3 < end; e += 4) {
        int c0 = __ldg(&col[e]);
        int c1 = __ldg(&col[e + 1]);
        int c2 = __ldg(&col[e + 2]);
        int c3 = __ldg(&col[e + 3]);

        // att first: streaming loads with the longest latency.
        float a0 = __ldg(&att[(e    ) * 4 + hd]);
        float a1 = __ldg(&att[(e + 1) * 4 + hd]);
        float a2 = __ldg(&att[(e + 2) * 4 + hd]);
        float a3 = __ldg(&att[(e + 3) * 4 + hd]);

        c0 = min(max(c0, 0), nmax);
        c1 = min(max(c1, 0), nmax);
        c2 = min(max(c2, 0), nmax);
        c3 = min(max(c3, 0), nmax);

        float4 h0 = __ldg((const float4*)(hfeat + c0 * 32 + q * 4));
        float4 h1 = __ldg((const float4*)(hfeat + c1 * 32 + q * 4));
        float4 h2 = __ldg((const float4*)(hfeat + c2 * 32 + q * 4));
        float4 h3 = __ldg((const float4*)(hfeat + c3 * 32 + q * 4));

        acc.x = fmaf(a0, h0.x, acc.x);
        acc.y = fmaf(a0, h0.y, acc.y);
        acc.z = fmaf(a0, h0.z, acc.z);
        acc.w = fmaf(a0, h0.w, acc.w);
        acc.x = fmaf(a1, h1.x, acc.x);
        acc.y = fmaf(a1, h1.y, acc.y);
        acc.z = fmaf(a1, h1.z, acc.z);
        acc.w = fmaf(a1, h1.w, acc.w);
        acc.x = fmaf(a2, h2.x, acc.x);
        acc.y = fmaf(a2, h2.y, acc.y);
        acc.z = fmaf(a2, h2.z, acc.z);
        acc.w = fmaf(a2, h2.w, acc.w);
        acc.x = fmaf(a3, h3.x, acc.x);
        acc.y = fmaf(a3, h3.y, acc.y);
        acc.z = fmaf(a3, h3.z, acc.z);
        acc.w = fmaf(a3, h3.w, acc.w);
    }
    // Scalar tail (<=3 iterations), also divergent.
    for (; e < end; ++e) {
        int c = __ldg(&col[e]);
        c = min(max(c, 0), nmax);
        float a = __ldg(&att[e * 4 + hd]);
        float4 h0 = __ldg((const float4*)(hfeat + c * 32 + q * 4));
        acc.x = fmaf(a, h0.x, acc.x);
        acc.y = fmaf(a, h0.y, acc.y);
        acc.z = fmaf(a, h0.z, acc.z);
        acc.w = fmaf(a, h0.w, acc.w);
    }

    // Warp stores 4 rows * 32 floats = 512B contiguous; zeros for empty rows.
    ((float4*)out)[r * 8 + q] = acc;
}

extern "C" void kernel_launch(void* const* d_in, const int* in_sizes, int n_in,
                              void* d_out, int out_size) {
    const int*   row  = (const int*)  d_in[0];
    const int*   col  = (const int*)  d_in[1];
    const float* att  = (const float*)d_in[2];
    const float* hft  = (const float*)d_in[3];
    float*       out  = (float*)      d_out;

    int E = in_sizes[0];
    int N = in_sizes[3] / 32;  // h is (N, 4, 8)

    {
        int threads = 256;
        int blocks = (E + threads - 1) / threads;
        build_row_ptr_kernel<<<blocks, threads>>>(row, E, N);
    }
    {
        int threads = 64;                      // 2 warps = 8 rows per block
        int rows_per_block = (threads / 32) * 4;
        int blocks = (N + rows_per_block - 1) / rows_per_block;
        spmm_group_div_kernel<<<blocks, threads>>>(col, att, hft, out, N);
    }
}